// round 7
// baseline (speedup 1.0000x reference)
#include <cuda_runtime.h>
#include <cuda_bf16.h>

// Problem constants (fixed by setup_inputs): B=8, N=128, T=1024, K=3
#define BB   8
#define NN   128
#define TT   1024
#define ITERS (TT / 256)   // 4

__global__ __launch_bounds__(256) void fused_arc_conv_kernel(
    const float* __restrict__ k,
    const float* __restrict__ leak,
    const float* __restrict__ alpha,
    const float* __restrict__ beta,
    float* __restrict__ out)
{
    __shared__ __align__(8) float2 scd[TT + 2];   // (c0, c1*k_ntk) staged per point

    const int row = blockIdx.x;          // 0 .. B*B*N-1, layout (i,j,n)
    const int n   = row & (NN - 1);
    const int ij  = row >> 7;
    const int j   = ij & (BB - 1);
    const int i   = ij >> 3;

    const float a  = fmaxf(leak[0], 0.0f);
    const float w0 = fmaxf(alpha[0], 0.0f);
    const float w1 = fmaxf(alpha[1], 0.0f);
    const float w2 = fmaxf(alpha[2], 0.0f);
    const float bv = fmaxf(beta[0], 0.0f);

    const float PIf    = 3.14159265358979323846f;
    const float one_m  = (1.0f - a) * (1.0f - a);
    const float coef   = 1.0f + a * a;
    const float inv2pi = 1.0f / (2.0f * PIf);
    const float RL     = 1.0f - 1e-6f;
    const float EPS    = 1e-12f;
    // one_m == 0  <=>  a == 1  =>  coef == 2, theta/s terms vanish analytically
    const bool  fast   = (one_m == 0.0f);

    const float2* __restrict__ krow = reinterpret_cast<const float2*>(k) + (size_t)row * TT;
    float2* __restrict__ orow       = reinterpret_cast<float2*>(out)     + (size_t)row * TT;
    // diagonal rows (i,i,0,:) and (j,j,0,:) carrying the variance vectors.
    // 8 rows x 8KB = 64KB total: L1/L2 resident across the whole launch.
    const float2* __restrict__ kdi = reinterpret_cast<const float2*>(k) + (size_t)(i * BB + i) * NN * TT;
    const float2* __restrict__ kdj = reinterpret_cast<const float2*>(k) + (size_t)(j * BB + j) * NN * TT;

    const int tid = threadIdx.x;

    float c0r[ITERS], dr[ITERS];

    // ---------- phase 1: pointwise (moderate MLP: 2 iterations batched) ----------
    #pragma unroll 2
    for (int it = 0; it < ITERS; ++it) {
        const int t = it * 256 + tid;
        const float2 kv = krow[t];
        const float  vx = kdi[t].x;                       // v[i, t]
        const int    ty = n + t;
        const float  vy = (ty < TT) ? kdj[ty].x : 0.0f;   // v_pad[j, n+t]
        const float sxy = sqrtf(fmaxf(vx, 0.0f) * fmaxf(vy, 0.0f));

        float c0v, dv;
        if (fast) {
            const float lim = RL * sxy;                   // halfcoef == 1 here
            c0v = fminf(fmaxf(kv.x, -lim), lim);
            dv  = kv.y;
        } else {
            const float denom = fmaxf(sxy, EPS);
            float rho = fminf(fmaxf(kv.x / denom, -RL), RL);
            const float theta = acosf(rho);
            const float s     = sqrtf(fmaxf(1.0f - rho * rho, 0.0f));
            const float tpart = coef * PIf - one_m * theta;
            c0v = sxy * inv2pi * (one_m * s + rho * tpart);
            dv  = tpart * inv2pi * kv.y;
        }
        c0r[it] = c0v;
        dr[it]  = dv;
        scd[t + 1] = make_float2(c0v, dv);
    }
    if (tid == 0) {
        scd[0]      = make_float2(0.0f, 0.0f);
        scd[TT + 1] = make_float2(0.0f, 0.0f);
    }
    __syncthreads();

    // ---------- phase 2: 3-tap conv (centers in regs, halo pairs via LDS.64) ----------
    #pragma unroll
    for (int it = 0; it < ITERS; ++it) {
        const int t = it * 256 + tid;
        const float2 L = scd[t];
        const float2 R = scd[t + 2];
        const float kg = w0 * L.x + w1 * c0r[it] + w2 * R.x;
        const float kn = w0 * L.y + w1 * dr[it]  + w2 * R.y + kg;
        orow[t] = make_float2(kg + bv, kn + bv);
    }
}

extern "C" void kernel_launch(void* const* d_in, const int* in_sizes, int n_in,
                              void* d_out, int out_size) {
    const float* k     = (const float*)d_in[0];
    const float* leak  = (const float*)d_in[1];
    const float* alpha = (const float*)d_in[2];
    const float* beta  = (const float*)d_in[3];
    float* out = (float*)d_out;

    fused_arc_conv_kernel<<<BB * BB * NN, 256>>>(k, leak, alpha, beta, out);
}

// round 8
// speedup vs baseline: 1.1895x; 1.1895x over previous
#include <cuda_runtime.h>
#include <cuda_bf16.h>

// Problem constants (fixed by setup_inputs): B=8, N=128, T=1024, K=3
#define BB   8
#define NN   128
#define TT   1024
#define ITERS (TT / 256)   // 4

__global__ __launch_bounds__(256) void fused_arc_conv_kernel(
    const float* __restrict__ k,
    const float* __restrict__ leak,
    const float* __restrict__ alpha,
    const float* __restrict__ beta,
    float* __restrict__ out)
{
    __shared__ float s0[TT + 2];
    __shared__ float s1[TT + 2];

    const int row = blockIdx.x;          // 0 .. B*B*N-1, layout (i,j,n)
    const int n   = row & (NN - 1);
    const int ij  = row >> 7;
    const int j   = ij & (BB - 1);
    const int i   = ij >> 3;

    const float a  = fmaxf(leak[0], 0.0f);
    const float w0 = fmaxf(alpha[0], 0.0f);
    const float w1 = fmaxf(alpha[1], 0.0f);
    const float w2 = fmaxf(alpha[2], 0.0f);
    const float bv = fmaxf(beta[0], 0.0f);

    const float PIf    = 3.14159265358979323846f;
    const float one_m  = (1.0f - a) * (1.0f - a);
    const float coef   = 1.0f + a * a;
    const float halfcoef = 0.5f * coef;
    const float inv2pi = 1.0f / (2.0f * PIf);
    const float RL     = 1.0f - 1e-6f;
    const float EPS    = 1e-12f;
    const bool  fast   = (one_m == 0.0f);   // leak == 1 -> halfcoef == 1

    const float2* __restrict__ krow = reinterpret_cast<const float2*>(k) + (size_t)row * TT;
    float2* __restrict__ orow       = reinterpret_cast<float2*>(out)     + (size_t)row * TT;
    // diagonal rows (i,i,0,:) / (j,j,0,:) carrying variance; L1/L2-resident (64KB total)
    const float2* __restrict__ kdi = reinterpret_cast<const float2*>(k) + (size_t)(i * BB + i) * NN * TT;
    const float2* __restrict__ kdj = reinterpret_cast<const float2*>(k) + (size_t)(j * BB + j) * NN * TT;

    const int tid = threadIdx.x;

    float c0r[ITERS], dr[ITERS];

    // ---------- phase 1: pointwise, loads+compute+STS interleaved per iteration ----------
    #pragma unroll
    for (int it = 0; it < ITERS; ++it) {
        const int t  = it * 256 + tid;
        const float2 kv = krow[t];
        const float  vx = kdi[t].x;                       // v[i, t]
        const int    ty = n + t;
        const float  vy = (ty < TT) ? kdj[ty].x : 0.0f;   // v_pad[j, n+t]
        const float sxy = sqrtf(fmaxf(vx, 0.0f) * fmaxf(vy, 0.0f));

        float c0v, dv;
        if (fast) {
            const float lim = RL * sxy;
            c0v = fminf(fmaxf(kv.x, -lim), lim);
            dv  = kv.y;
        } else {
            const float denom = fmaxf(sxy, EPS);
            float rho = fminf(fmaxf(kv.x / denom, -RL), RL);
            const float theta = acosf(rho);
            const float s     = sqrtf(fmaxf(1.0f - rho * rho, 0.0f));
            const float tpart = coef * PIf - one_m * theta;
            c0v = sxy * inv2pi * (one_m * s + rho * tpart) * (2.0f * halfcoef / coef); // == sxy*inv2pi*(...)
            dv  = tpart * inv2pi * kv.y;
        }
        c0r[it] = c0v;
        dr[it]  = dv;
        s0[t + 1] = c0v;
        s1[t + 1] = dv;
    }
    if (tid == 0) {
        s0[0] = 0.0f; s1[0] = 0.0f;
        s0[TT + 1] = 0.0f; s1[TT + 1] = 0.0f;
    }
    __syncthreads();

    // ---------- phase 2: 3-tap conv; output stored evict-first to protect k in L2 ----------
    #pragma unroll
    for (int it = 0; it < ITERS; ++it) {
        const int t = it * 256 + tid;
        const float kg = w0 * s0[t] + w1 * c0r[it] + w2 * s0[t + 2];
        const float kn = w0 * s1[t] + w1 * dr[it]  + w2 * s1[t + 2] + kg;
        __stcs(&orow[t], make_float2(kg + bv, kn + bv));
    }
}

extern "C" void kernel_launch(void* const* d_in, const int* in_sizes, int n_in,
                              void* d_out, int out_size) {
    const float* k     = (const float*)d_in[0];
    const float* leak  = (const float*)d_in[1];
    const float* alpha = (const float*)d_in[2];
    const float* beta  = (const float*)d_in[3];
    float* out = (float*)d_out;

    fused_arc_conv_kernel<<<BB * BB * NN, 256>>>(k, leak, alpha, beta, out);
}

// round 9
// speedup vs baseline: 1.2926x; 1.0867x over previous
#include <cuda_runtime.h>
#include <cuda_bf16.h>

// Problem constants (fixed by setup_inputs): B=8, N=128, T=1024, K=3
#define BB   8
#define NN   128
#define TT   1024
#define ITERS (TT / 256)   // 4

__global__ __launch_bounds__(256, 8) void fused_arc_conv_kernel(
    const float* __restrict__ k,
    const float* __restrict__ leak,
    const float* __restrict__ alpha,
    const float* __restrict__ beta,
    float* __restrict__ out)
{
    __shared__ float s0[TT + 2];
    __shared__ float s1[TT + 2];

    const int row = blockIdx.x;          // 0 .. B*B*N-1, layout (i,j,n)
    const int n   = row & (NN - 1);
    const int ij  = row >> 7;
    const int j   = ij & (BB - 1);
    const int i   = ij >> 3;

    const float a  = fmaxf(leak[0], 0.0f);
    const float w0 = fmaxf(alpha[0], 0.0f);
    const float w1 = fmaxf(alpha[1], 0.0f);
    const float w2 = fmaxf(alpha[2], 0.0f);
    const float bv = fmaxf(beta[0], 0.0f);

    const float PIf    = 3.14159265358979323846f;
    const float one_m  = (1.0f - a) * (1.0f - a);
    const float coef   = 1.0f + a * a;
    const float inv2pi = 1.0f / (2.0f * PIf);
    const float RL     = 1.0f - 1e-6f;
    const float EPS    = 1e-12f;
    const bool  fast   = (one_m == 0.0f);   // leak == 1 -> coef == 2 -> halfcoef == 1

    const float2* __restrict__ krow = reinterpret_cast<const float2*>(k) + (size_t)row * TT;
    float2* __restrict__ orow       = reinterpret_cast<float2*>(out)     + (size_t)row * TT;
    // diagonal rows (i,i,0,:) / (j,j,0,:) carrying variance; L1/L2-resident (64KB total)
    const float2* __restrict__ kdi = reinterpret_cast<const float2*>(k) + (size_t)(i * BB + i) * NN * TT;
    const float2* __restrict__ kdj = reinterpret_cast<const float2*>(k) + (size_t)(j * BB + j) * NN * TT;

    const int tid = threadIdx.x;

    float c0r[ITERS], dr[ITERS];

    // ---------- phase 1: pointwise, loads+compute+STS interleaved per iteration ----------
    #pragma unroll
    for (int it = 0; it < ITERS; ++it) {
        const int t  = it * 256 + tid;
        const float2 kv = krow[t];
        const float  vx = kdi[t].x;                       // v[i, t]
        const int    ty = n + t;
        const float  vy = (ty < TT) ? kdj[ty].x : 0.0f;   // v_pad[j, n+t]
        const float sxy = sqrtf(fmaxf(vx, 0.0f) * fmaxf(vy, 0.0f));

        float c0v, dv;
        if (fast) {
            const float lim = RL * sxy;
            c0v = fminf(fmaxf(kv.x, -lim), lim);
            dv  = kv.y;
        } else {
            const float denom = fmaxf(sxy, EPS);
            float rho = fminf(fmaxf(kv.x / denom, -RL), RL);
            const float theta = acosf(rho);
            const float s     = sqrtf(fmaxf(1.0f - rho * rho, 0.0f));
            const float tpart = coef * PIf - one_m * theta;
            c0v = sxy * inv2pi * (one_m * s + rho * tpart);
            dv  = tpart * inv2pi * kv.y;
        }
        c0r[it] = c0v;
        dr[it]  = dv;
        s0[t + 1] = c0v;
        s1[t + 1] = dv;
    }
    if (tid == 0) {
        s0[0] = 0.0f; s1[0] = 0.0f;
        s0[TT + 1] = 0.0f; s1[TT + 1] = 0.0f;
    }
    __syncthreads();

    // ---------- phase 2: 3-tap conv; output stored evict-first to protect k in L2 ----------
    #pragma unroll
    for (int it = 0; it < ITERS; ++it) {
        const int t = it * 256 + tid;
        const float kg = w0 * s0[t] + w1 * c0r[it] + w2 * s0[t + 2];
        const float kn = w0 * s1[t] + w1 * dr[it]  + w2 * s1[t + 2] + kg;
        __stcs(&orow[t], make_float2(kg + bv, kn + bv));
    }
}

extern "C" void kernel_launch(void* const* d_in, const int* in_sizes, int n_in,
                              void* d_out, int out_size) {
    const float* k     = (const float*)d_in[0];
    const float* leak  = (const float*)d_in[1];
    const float* alpha = (const float*)d_in[2];
    const float* beta  = (const float*)d_in[3];
    float* out = (float*)d_out;

    fused_arc_conv_kernel<<<BB * BB * NN, 256>>>(k, leak, alpha, beta, out);
}

// round 10
// speedup vs baseline: 1.3347x; 1.0326x over previous
#include <cuda_runtime.h>
#include <cuda_bf16.h>

// Problem constants (fixed by setup_inputs): B=8, N=128, T=1024, K=3
#define BB   8
#define NN   128
#define TT   1024
#define ITERS (TT / 512)   // 2 (each thread does a pair of points per iter)

__global__ __launch_bounds__(256, 8) void fused_arc_conv_kernel(
    const float* __restrict__ k,
    const float* __restrict__ leak,
    const float* __restrict__ alpha,
    const float* __restrict__ beta,
    float* __restrict__ out)
{
    // point t lives at index t+2 (so pair stores at even indices are 8B-aligned)
    __shared__ __align__(16) float s0[TT + 4];
    __shared__ __align__(16) float s1[TT + 4];

    const int row = blockIdx.x;          // 0 .. B*B*N-1, layout (i,j,n)
    const int n   = row & (NN - 1);
    const int ij  = row >> 7;
    const int j   = ij & (BB - 1);
    const int i   = ij >> 3;

    const float a  = fmaxf(leak[0], 0.0f);
    const float w0 = fmaxf(alpha[0], 0.0f);
    const float w1 = fmaxf(alpha[1], 0.0f);
    const float w2 = fmaxf(alpha[2], 0.0f);
    const float bv = fmaxf(beta[0], 0.0f);

    const float PIf    = 3.14159265358979323846f;
    const float one_m  = (1.0f - a) * (1.0f - a);
    const float coef   = 1.0f + a * a;
    const float inv2pi = 1.0f / (2.0f * PIf);
    const float RL     = 1.0f - 1e-6f;
    const float EPS    = 1e-12f;
    const bool  fast   = (one_m == 0.0f);   // leak == 1 -> halfcoef == 1

    const float2* __restrict__ krow = reinterpret_cast<const float2*>(k) + (size_t)row * TT;
    float2* __restrict__ orow       = reinterpret_cast<float2*>(out)     + (size_t)row * TT;
    // diagonal rows (i,i,0,:) / (j,j,0,:) carrying variance; L1/L2-resident (64KB total)
    const float2* __restrict__ kdi = reinterpret_cast<const float2*>(k) + (size_t)(i * BB + i) * NN * TT;
    const float2* __restrict__ kdj = reinterpret_cast<const float2*>(k) + (size_t)(j * BB + j) * NN * TT;

    const int tid = threadIdx.x;

    float c0a[ITERS], c0b[ITERS], da[ITERS], db[ITERS];

    // ---------- phase 1: pairwise pointwise ----------
    #pragma unroll
    for (int it = 0; it < ITERS; ++it) {
        const int p = it * 512 + tid * 2;                 // even
        const float4 kv4 = *reinterpret_cast<const float4*>(krow + p); // (gp0,ntk0,gp1,ntk1)
        const float4 vx4 = *reinterpret_cast<const float4*>(kdi + p);  // (vx0, -, vx1, -)
        const int ty0 = n + p, ty1 = n + p + 1;
        const float vy0 = (ty0 < TT) ? kdj[ty0].x : 0.0f;
        const float vy1 = (ty1 < TT) ? kdj[ty1].x : 0.0f;

        const float sxy0 = sqrtf(fmaxf(vx4.x, 0.0f) * fmaxf(vy0, 0.0f));
        const float sxy1 = sqrtf(fmaxf(vx4.z, 0.0f) * fmaxf(vy1, 0.0f));

        float c00, d0, c01, d1;
        if (fast) {
            const float l0 = RL * sxy0;
            const float l1 = RL * sxy1;
            c00 = fminf(fmaxf(kv4.x, -l0), l0);  d0 = kv4.y;
            c01 = fminf(fmaxf(kv4.z, -l1), l1);  d1 = kv4.w;
        } else {
            const float dn0 = fmaxf(sxy0, EPS);
            float rho0 = fminf(fmaxf(kv4.x / dn0, -RL), RL);
            const float th0 = acosf(rho0);
            const float sn0 = sqrtf(fmaxf(1.0f - rho0 * rho0, 0.0f));
            const float tp0 = coef * PIf - one_m * th0;
            c00 = sxy0 * inv2pi * (one_m * sn0 + rho0 * tp0);
            d0  = tp0 * inv2pi * kv4.y;

            const float dn1 = fmaxf(sxy1, EPS);
            float rho1 = fminf(fmaxf(kv4.z / dn1, -RL), RL);
            const float th1 = acosf(rho1);
            const float sn1 = sqrtf(fmaxf(1.0f - rho1 * rho1, 0.0f));
            const float tp1 = coef * PIf - one_m * th1;
            c01 = sxy1 * inv2pi * (one_m * sn1 + rho1 * tp1);
            d1  = tp1 * inv2pi * kv4.w;
        }
        c0a[it] = c00; c0b[it] = c01;
        da[it]  = d0;  db[it]  = d1;
        *reinterpret_cast<float2*>(&s0[p + 2]) = make_float2(c00, c01);
        *reinterpret_cast<float2*>(&s1[p + 2]) = make_float2(d0, d1);
    }
    if (tid == 0) {
        s0[1] = 0.0f; s1[1] = 0.0f;             // point -1
        s0[TT + 2] = 0.0f; s1[TT + 2] = 0.0f;   // point TT
    }
    __syncthreads();

    // ---------- phase 2: 3-tap conv; pair neighbors in regs, 2 halo LDS per array ----------
    #pragma unroll
    for (int it = 0; it < ITERS; ++it) {
        const int p = it * 512 + tid * 2;
        const float L0 = s0[p + 1];   // point p-1
        const float R0 = s0[p + 4];   // point p+2
        const float L1 = s1[p + 1];
        const float R1 = s1[p + 4];

        const float kg0 = w0 * L0      + w1 * c0a[it] + w2 * c0b[it];
        const float kg1 = w0 * c0a[it] + w1 * c0b[it] + w2 * R0;
        const float kn0 = w0 * L1      + w1 * da[it]  + w2 * db[it] + kg0;
        const float kn1 = w0 * da[it]  + w1 * db[it]  + w2 * R1     + kg1;

        __stcs(reinterpret_cast<float4*>(orow + p),
               make_float4(kg0 + bv, kn0 + bv, kg1 + bv, kn1 + bv));
    }
}

extern "C" void kernel_launch(void* const* d_in, const int* in_sizes, int n_in,
                              void* d_out, int out_size) {
    const float* k     = (const float*)d_in[0];
    const float* leak  = (const float*)d_in[1];
    const float* alpha = (const float*)d_in[2];
    const float* beta  = (const float*)d_in[3];
    float* out = (float*)d_out;

    fused_arc_conv_kernel<<<BB * BB * NN, 256>>>(k, leak, alpha, beta, out);
}

// round 11
// speedup vs baseline: 1.4386x; 1.0779x over previous
#include <cuda_runtime.h>
#include <cuda_bf16.h>

// Problem constants (fixed by setup_inputs): B=8, N=128, T=1024, K=3
#define BB   8
#define NN   128
#define TT   1024
#define ITERS (TT / 512)   // 2 (each thread does a pair of points per iter)
#define NWARP 8

__global__ __launch_bounds__(256, 8) void fused_arc_conv_kernel(
    const float* __restrict__ k,
    const float* __restrict__ leak,
    const float* __restrict__ alpha,
    const float* __restrict__ beta,
    float* __restrict__ out)
{
    // warp-boundary exchange only: first (lane0) and last (lane31) point of each warp
    __shared__ float2 sFirst[ITERS][NWARP];   // (c0a, da) at lane 0
    __shared__ float2 sLast[ITERS][NWARP];    // (c0b, db) at lane 31

    const int row = blockIdx.x;          // 0 .. B*B*N-1, layout (i,j,n)
    const int n   = row & (NN - 1);
    const int ij  = row >> 7;
    const int j   = ij & (BB - 1);
    const int i   = ij >> 3;

    const float a  = fmaxf(leak[0], 0.0f);
    const float w0 = fmaxf(alpha[0], 0.0f);
    const float w1 = fmaxf(alpha[1], 0.0f);
    const float w2 = fmaxf(alpha[2], 0.0f);
    const float bv = fmaxf(beta[0], 0.0f);

    const float PIf    = 3.14159265358979323846f;
    const float one_m  = (1.0f - a) * (1.0f - a);
    const float coef   = 1.0f + a * a;
    const float inv2pi = 1.0f / (2.0f * PIf);
    const float RL     = 1.0f - 1e-6f;
    const float EPS    = 1e-12f;
    const bool  fast   = (one_m == 0.0f);   // leak == 1 -> halfcoef == 1

    const float2* __restrict__ krow = reinterpret_cast<const float2*>(k) + (size_t)row * TT;
    float2* __restrict__ orow       = reinterpret_cast<float2*>(out)     + (size_t)row * TT;
    // diagonal rows (i,i,0,:) / (j,j,0,:) carrying variance; L1/L2-resident (64KB total)
    const float2* __restrict__ kdi = reinterpret_cast<const float2*>(k) + (size_t)(i * BB + i) * NN * TT;
    const float2* __restrict__ kdj = reinterpret_cast<const float2*>(k) + (size_t)(j * BB + j) * NN * TT;

    const int tid  = threadIdx.x;
    const int warp = tid >> 5;
    const int lane = tid & 31;
    const unsigned FULL = 0xffffffffu;

    float c0a[ITERS], c0b[ITERS], da[ITERS], db[ITERS];

    // ---------- phase 1: pairwise pointwise (registers only) ----------
    #pragma unroll
    for (int it = 0; it < ITERS; ++it) {
        const int p = it * 512 + tid * 2;                 // even
        const float4 kv4 = *reinterpret_cast<const float4*>(krow + p); // (gp0,ntk0,gp1,ntk1)
        const float4 vx4 = *reinterpret_cast<const float4*>(kdi + p);  // (vx0, -, vx1, -)
        const int ty0 = n + p, ty1 = n + p + 1;
        const float vy0 = (ty0 < TT) ? kdj[ty0].x : 0.0f;
        const float vy1 = (ty1 < TT) ? kdj[ty1].x : 0.0f;

        const float sxy0 = sqrtf(fmaxf(vx4.x, 0.0f) * fmaxf(vy0, 0.0f));
        const float sxy1 = sqrtf(fmaxf(vx4.z, 0.0f) * fmaxf(vy1, 0.0f));

        float c00, d0, c01, d1;
        if (fast) {
            const float l0 = RL * sxy0;
            const float l1 = RL * sxy1;
            c00 = fminf(fmaxf(kv4.x, -l0), l0);  d0 = kv4.y;
            c01 = fminf(fmaxf(kv4.z, -l1), l1);  d1 = kv4.w;
        } else {
            const float dn0 = fmaxf(sxy0, EPS);
            float rho0 = fminf(fmaxf(kv4.x / dn0, -RL), RL);
            const float th0 = acosf(rho0);
            const float sn0 = sqrtf(fmaxf(1.0f - rho0 * rho0, 0.0f));
            const float tp0 = coef * PIf - one_m * th0;
            c00 = sxy0 * inv2pi * (one_m * sn0 + rho0 * tp0);
            d0  = tp0 * inv2pi * kv4.y;

            const float dn1 = fmaxf(sxy1, EPS);
            float rho1 = fminf(fmaxf(kv4.z / dn1, -RL), RL);
            const float th1 = acosf(rho1);
            const float sn1 = sqrtf(fmaxf(1.0f - rho1 * rho1, 0.0f));
            const float tp1 = coef * PIf - one_m * th1;
            c01 = sxy1 * inv2pi * (one_m * sn1 + rho1 * tp1);
            d1  = tp1 * inv2pi * kv4.w;
        }
        c0a[it] = c00; c0b[it] = c01;
        da[it]  = d0;  db[it]  = d1;
        if (lane == 0)  sFirst[it][warp] = make_float2(c00, d0);
        if (lane == 31) sLast[it][warp]  = make_float2(c01, d1);
    }
    __syncthreads();

    // ---------- phase 2: 3-tap conv; halos via shfl, warp boundaries via tiny smem ----------
    #pragma unroll
    for (int it = 0; it < ITERS; ++it) {
        const int p = it * 512 + tid * 2;

        float Lc = __shfl_up_sync(FULL, c0b[it], 1);    // point p-1 c0
        float Ld = __shfl_up_sync(FULL, db[it], 1);     // point p-1 d
        float Rc = __shfl_down_sync(FULL, c0a[it], 1);  // point p+2 c0
        float Rd = __shfl_down_sync(FULL, da[it], 1);   // point p+2 d

        if (lane == 0) {
            float2 v = make_float2(0.0f, 0.0f);
            if (warp > 0)        v = sLast[it][warp - 1];
            else if (it > 0)     v = sLast[it - 1][NWARP - 1];
            Lc = v.x; Ld = v.y;
        }
        if (lane == 31) {
            float2 v = make_float2(0.0f, 0.0f);
            if (warp < NWARP - 1)   v = sFirst[it][warp + 1];
            else if (it < ITERS - 1) v = sFirst[it + 1][0];
            Rc = v.x; Rd = v.y;
        }

        const float kg0 = w0 * Lc      + w1 * c0a[it] + w2 * c0b[it];
        const float kg1 = w0 * c0a[it] + w1 * c0b[it] + w2 * Rc;
        const float kn0 = w0 * Ld      + w1 * da[it]  + w2 * db[it] + kg0;
        const float kn1 = w0 * da[it]  + w1 * db[it]  + w2 * Rd     + kg1;

        __stcs(reinterpret_cast<float4*>(orow + p),
               make_float4(kg0 + bv, kn0 + bv, kg1 + bv, kn1 + bv));
    }
}

extern "C" void kernel_launch(void* const* d_in, const int* in_sizes, int n_in,
                              void* d_out, int out_size) {
    const float* k     = (const float*)d_in[0];
    const float* leak  = (const float*)d_in[1];
    const float* alpha = (const float*)d_in[2];
    const float* beta  = (const float*)d_in[3];
    float* out = (float*)d_out;

    fused_arc_conv_kernel<<<BB * BB * NN, 256>>>(k, leak, alpha, beta, out);
}